// round 13
// baseline (speedup 1.0000x reference)
#include <cuda_runtime.h>

// Problem constants
#define NV    32
#define DM    256
#define MM    128
#define DN    64
#define NL    3
#define BATCH 512
#define RPB   4                    // batch rows per block
#define NBLK  (BATCH / RPB)        // 128 blocks
#define NT    1024                 // threads per block (8 warps/SMSP)
#define AROW  130                  // activation buffer row stride (ull = float2), even

// Scratch (device globals: no allocations allowed)
__device__ float g_noise[BATCH * NV * DM];       // 16 MB: gelu(nz @ ne_W + ne_b)
__device__ float g_wpack[2686976];               // K-parity packed weights

// offsets into g_wpack (floats)
#define OFF_PA  0
#define OFF_W1  65536
#define OFF_W2  1114112
#define OFF_W3  1638400

typedef unsigned long long ull;

// ---- packed f32x2 helpers ----
__device__ __forceinline__ ull pack2(float w) {
    ull r; asm("mov.b64 %0, {%1, %1};" : "=l"(r) : "f"(w)); return r;
}
__device__ __forceinline__ ull pack2f(float a, float b) {
    ull r; asm("mov.b64 %0, {%1, %2};" : "=l"(r) : "f"(a), "f"(b)); return r;
}
__device__ __forceinline__ void ffma2(ull &acc, ull x, ull w) {
    asm("fma.rn.f32x2 %0, %1, %2, %3;" : "=l"(acc) : "l"(x), "l"(w), "l"(acc));
}
__device__ __forceinline__ ull fadd2(ull a, ull b) {
    ull r; asm("add.rn.f32x2 %0, %1, %2;" : "=l"(r) : "l"(a), "l"(b)); return r;
}
__device__ __forceinline__ float2 asf2(ull a) {
    float2 f; asm("mov.b64 {%0, %1}, %2;" : "=f"(f.x), "=f"(f.y) : "l"(a)); return f;
}
__device__ __forceinline__ float lanesum(ull a) {
    float2 f = asf2(a); return f.x + f.y;
}
__device__ __forceinline__ float gelu(float x) {
    return 0.5f * x * (1.0f + erff(x * 0.7071067811865476f));   // exact erf GELU
}

// ============================================================================
// Single pack kernel for all 4 weight tensors.
// Layout: Wp[d2][parity][N] <- W[2*d2 + parity][N]  (R9 layout)
// ============================================================================
__global__ void pack_all_kernel(
    const float* __restrict__ paW, const float* __restrict__ mW1,
    const float* __restrict__ mW2, const float* __restrict__ mW3)
{
    const int z   = blockIdx.z;
    const int var = blockIdx.y;
    int K, N, off;
    const float* src;
    if      (z == 0) { if (var) return; K = DM; N = DM; off = OFF_PA; src = paW; }
    else if (z == 1) { K = DM; N = MM; off = OFF_W1; src = mW1; }
    else if (z == 2) { K = MM; N = MM; off = OFF_W2; src = mW2; }
    else             { K = MM; N = DM; off = OFF_W3; src = mW3; }

    const int  total = K * N;
    const float* __restrict__ s = src + (size_t)var * total;
    float* __restrict__ d = g_wpack + off + (size_t)var * total;
    for (int idx = blockIdx.x * blockDim.x + threadIdx.x; idx < total;
         idx += gridDim.x * blockDim.x) {
        int d2  = idx / (2 * N);
        int rem = idx - d2 * (2 * N);
        int p   = rem / N;
        int j   = rem - p * N;
        d[idx] = s[(2 * d2 + p) * N + j];
    }
}

// ============================================================================
// Kernel: noise encoder precompute
// ============================================================================
__global__ void __launch_bounds__(256, 2) noise_kernel(
    const float* __restrict__ nz,
    const float* __restrict__ neW,
    const float* __restrict__ neb)
{
    const int i = blockIdx.y;
    const int chunk = blockIdx.x;
    const int d = threadIdx.x;

    __shared__ __align__(16) ull s_nzp[DN][16];
    for (int idx = d; idx < DN * 16; idx += 256) {
        int k = idx >> 4, rp = idx & 15;
        int b = chunk * 32 + rp * 2;
        s_nzp[k][rp] = pack2f(nz[(b * NV + i) * DN + k],
                              nz[((b + 1) * NV + i) * DN + k]);
    }
    __syncthreads();

    ull acc[16];
    #pragma unroll
    for (int rp = 0; rp < 16; rp++) acc[rp] = 0;

    const float* __restrict__ W = neW + i * DN * DM + d;
    #pragma unroll 2
    for (int k = 0; k < DN; k++) {
        ull w2 = pack2(__ldg(W + k * DM));
        const ulonglong2* row = reinterpret_cast<const ulonglong2*>(s_nzp[k]);
        #pragma unroll
        for (int j = 0; j < 8; j++) {
            ulonglong2 x = row[j];
            ffma2(acc[2 * j],     x.x, w2);
            ffma2(acc[2 * j + 1], x.y, w2);
        }
    }
    const float bias = neb[i * DM + d];
    #pragma unroll
    for (int rp = 0; rp < 16; rp++) {
        float2 f = asf2(acc[rp]);
        int b = chunk * 32 + rp * 2;
        g_noise[((long long)b * NV + i) * DM + d]       = gelu(f.x + bias);
        g_noise[((long long)(b + 1) * NV + i) * DM + d] = gelu(f.y + bias);
    }
}

// ============================================================================
// Split-K partial GEMM (NT=1024). Thread = (cg, ks): 2 cols x 4 rows.
// acc = 8 ull (16 regs) to fit the 64-reg cap at 1024 threads.
// Weights: Wp[d2][parity][N], float2 loads; acts: LDS.128 (2 K-pairs).
// ============================================================================
struct WPre { float2 e0, o0, e1, o1; };

template<int N, int K>
__device__ __forceinline__ WPre wpref(const float* __restrict__ Wp, int t)
{
    constexpr int CG = N / 2;
    constexpr int KS = NT / CG;           // 8 (N=256) / 16 (N=128)
    constexpr int D2 = (K / KS) / 2;
    const int cg = t & (CG - 1);
    const int ks = t / CG;
    const float2* __restrict__ base =
        reinterpret_cast<const float2*>(Wp + (size_t)(ks * D2) * (2 * N)) + cg;
    WPre p;
    p.e0 = __ldg(base);
    p.o0 = __ldg(base + N / 2);
    p.e1 = __ldg(base + N);
    p.o1 = __ldg(base + 3 * (N / 2));
    return p;
}

template<int N, int K>
__device__ __forceinline__ void split_partial(
    const ull* __restrict__ sinu, float* __restrict__ red,
    const float* __restrict__ Wp, int t, WPre pre)
{
    constexpr int CG = N / 2;
    constexpr int KS = NT / CG;
    constexpr int D2 = (K / KS) / 2;
    const int cg = t & (CG - 1);
    const int ks = t / CG;
    const int j0 = cg * 2;

    ull acc[2][4];
    #pragma unroll
    for (int c = 0; c < 2; c++)
        #pragma unroll
        for (int r = 0; r < 4; r++) acc[c][r] = 0;

    const float2* __restrict__ w =
        reinterpret_cast<const float2*>(Wp + (size_t)(ks * D2) * (2 * N)) + cg;
    const ull* __restrict__ x = sinu + ks * D2;

    #pragma unroll
    for (int d = 0; d < D2; d += 2) {
        float2 we0 = (d == 0) ? pre.e0 : __ldg(w + d * N);
        float2 wo0 = (d == 0) ? pre.o0 : __ldg(w + d * N + N / 2);
        float2 we1 = (d == 0) ? pre.e1 : __ldg(w + (d + 1) * N);
        float2 wo1 = (d == 0) ? pre.o1 : __ldg(w + (d + 1) * N + N / 2);
        ull w00 = pack2f(we0.x, wo0.x);   // col j0,   K-pair d
        ull w01 = pack2f(we0.y, wo0.y);   // col j0+1, K-pair d
        ull w10 = pack2f(we1.x, wo1.x);   // col j0,   K-pair d+1
        ull w11 = pack2f(we1.y, wo1.y);   // col j0+1, K-pair d+1
        #pragma unroll
        for (int r = 0; r < 4; r++) {
            ulonglong2 xv = *reinterpret_cast<const ulonglong2*>(x + r * AROW + d);
            ffma2(acc[0][r], xv.x, w00);
            ffma2(acc[1][r], xv.x, w01);
            ffma2(acc[0][r], xv.y, w10);
            ffma2(acc[1][r], xv.y, w11);
        }
    }
    #pragma unroll
    for (int r = 0; r < 4; r++) {
        float2 o = make_float2(lanesum(acc[0][r]), lanesum(acc[1][r]));
        *reinterpret_cast<float2*>(red + (r * KS + ks) * N + j0) = o;
    }
}

// ---- reduce partials (tree) -> gelu -> activation buffer (float2 rows) ----
// N=256: threads t<512 (j2 = t&127, r = t>>7), KS=8
// N=128: threads t<256 (j2 = t&63,  r = t>>6), KS=16
template<int N>
__device__ __forceinline__ void reduce_act(
    const float* __restrict__ red, ull* __restrict__ soutu,
    const float* __restrict__ bias, int t)
{
    constexpr int KS = 2048 / N;
    constexpr int J2 = N / 2;
    const int j2 = t & (J2 - 1);
    const int r  = (N == 256) ? (t >> 7) : (t >> 6);
    const ull* __restrict__ rp = reinterpret_cast<const ull*>(red);
    ull v[KS];
    #pragma unroll
    for (int k = 0; k < KS; k++)
        v[k] = rp[(r * KS + k) * J2 + j2];
    #pragma unroll
    for (int stride = KS / 2; stride > 0; stride >>= 1)
        #pragma unroll
        for (int k = 0; k < stride; k++)
            v[k] = fadd2(v[k], v[k + stride]);
    const float2 bb = __ldg(reinterpret_cast<const float2*>(bias) + j2);
    ull s = fadd2(v[0], pack2f(bb.x, bb.y));
    float2 f = asf2(s);
    soutu[r * AROW + j2] = pack2f(gelu(f.x), gelu(f.y));
}

// ---- pc for NEXT target variable: all 512 items on threads 512..1023 ----
__device__ __forceinline__ void pc_part(
    int i, int tgt, int vmax,
    const float* __restrict__ s_val, const ull* __restrict__ s_adj2,
    const float* __restrict__ var_emb, ull* __restrict__ s_pc, int id)
{
    const int r  = id >> 7;
    const int j2 = id & 127;
    const float2 e = __ldg(reinterpret_cast<const float2*>(var_emb + tgt * DM) + j2);
    ull acc = pack2f(e.x, e.y);
    const float* vp = s_val + r * DM + j2 * 2;
    const ull* arow = s_adj2 + tgt * NV;
    #pragma unroll 4
    for (int v = 0; v < vmax; v++) {
        if (v == i) continue;                         // current var fused later
        ull x = *reinterpret_cast<const ull*>(vp + v * (4 * DM));
        ffma2(acc, x, arow[v]);
    }
    s_pc[r * AROW + j2] = acc;
}

// ============================================================================
// Main kernel
// ============================================================================
__global__ void __launch_bounds__(NT, 1) scm_kernel(
    const float* __restrict__ edge_logits,
    const float* __restrict__ var_emb,
    const float* __restrict__ pab,
    const float* __restrict__ mb1,
    const float* __restrict__ mb2,
    const float* __restrict__ mb3,
    float* __restrict__ out)
{
    extern __shared__ __align__(16) ull smem[];
    float* s_red  = reinterpret_cast<float*>(smem);          // 4096 ull = 32KB
    ull*   s_a    = smem + 4096;                             // 520 ull
    ull*   s_b    = smem + 4616;                             // 520 ull
    ull*   s_pc   = smem + 5136;                             // 520 ull
    ull*   s_adj2 = smem + 5656;                             // 1024 ull
    float* s_val  = reinterpret_cast<float*>(smem + 6680);   // 32768 fl = 128KB

    const int t = threadIdx.x;
    const int row0 = blockIdx.x * RPB;

    // adjacency: sigmoid((logits * offdiag)/0.5); diagonal -> 0.5 (splat ull)
    for (int idx = t; idx < NV * NV; idx += NT) {
        int ii = idx / NV, v = idx % NV;
        float z = (v == ii) ? 0.0f : edge_logits[v * NV + ii] * 2.0f;
        s_adj2[idx] = pack2(1.0f / (1.0f + expf(-z)));
    }
    // step 0 input: s_a = emb[0]
    if (t < 512) {
        const int j2 = t & 127;
        const int r  = t >> 7;
        const float2 e = __ldg(reinterpret_cast<const float2*>(var_emb) + j2);
        s_a[r * AROW + j2] = pack2f(e.x, e.y);
    }
    WPre pre_pa = wpref<DM, DM>(g_wpack + OFF_PA, t);
    __syncthreads();

    for (int s = 0; s < NL * NV; s++) {
        const int i = s & 31;
        const bool last = (s >= 2 * NV);
        const bool has_tgt = (s < NL * NV - 1);
        const int tgt = (i + 1) & 31;
        const int vmax = (s + 1 < NV) ? i : NV;

        // ---- pa: parent_input partials ; prefetch w1
        split_partial<DM, DM>(s_a, s_red, g_wpack + OFF_PA, t, pre_pa);
        WPre pre_w1 = wpref<MM, DM>(g_wpack + OFF_W1 + i * (DM * MM), t);
        __syncthreads();

        if (t < 512) reduce_act<DM>(s_red, s_b, pab, t);
        __syncthreads();

        // ---- w1: 256 -> 128 ; prefetch w2
        split_partial<MM, DM>(s_b, s_red, g_wpack + OFF_W1 + i * (DM * MM), t, pre_w1);
        WPre pre_w2 = wpref<MM, MM>(g_wpack + OFF_W2 + i * (MM * MM), t);
        __syncthreads();

        if (t < 256) reduce_act<MM>(s_red, s_a, mb1 + i * MM, t);
        else if (t >= 512 && has_tgt)
            pc_part(i, tgt, vmax, s_val, s_adj2, var_emb, s_pc, t - 512);
        __syncthreads();

        // ---- w2: 128 -> 128 ; prefetch w3
        split_partial<MM, MM>(s_a, s_red, g_wpack + OFF_W2 + i * (MM * MM), t, pre_w2);
        WPre pre_w3 = wpref<DM, MM>(g_wpack + OFF_W3 + i * (MM * DM), t);
        __syncthreads();

        if (t < 256) reduce_act<MM>(s_red, s_b, mb2 + i * MM, t);
        __syncthreads();

        // ---- w3: 128 -> 256 (partials) ; prefetch pa for next step
        split_partial<DM, MM>(s_b, s_red, g_wpack + OFF_W3 + i * (MM * DM), t, pre_w3);
        pre_pa = wpref<DM, DM>(g_wpack + OFF_PA, t);
        __syncthreads();

        // ---- final: sum partials (tree) + bias + noise -> s_val, out (last),
        //      fuse pc: s_a = s_pc + adj[i->tgt] * val_new
        if (t < 512) {
            const int j2 = t & 127;
            const int r  = t >> 7;
            const ull* rp = reinterpret_cast<const ull*>(s_red);
            ull v[8];
            #pragma unroll
            for (int k = 0; k < 8; k++)
                v[k] = rp[(r * 8 + k) * 128 + j2];
            #pragma unroll
            for (int stride = 4; stride > 0; stride >>= 1)
                #pragma unroll
                for (int k = 0; k < stride; k++)
                    v[k] = fadd2(v[k], v[k + stride]);
            const float2 b2 = __ldg(reinterpret_cast<const float2*>(mb3 + i * DM) + j2);
            long long gidx = ((long long)(row0 + r) * NV + i) * DM + j2 * 2;
            const float2 n2 = __ldg(reinterpret_cast<const float2*>(g_noise + gidx));
            float2 f = asf2(v[0]);
            float2 v2 = make_float2(f.x + b2.x + n2.x, f.y + b2.y + n2.y);
            *reinterpret_cast<float2*>(s_val + (i * 4 + r) * DM + j2 * 2) = v2;
            if (last) *reinterpret_cast<float2*>(out + gidx) = v2;
            if (has_tgt) {
                ull pcv = s_pc[r * AROW + j2];
                ffma2(pcv, pack2f(v2.x, v2.y), s_adj2[tgt * NV + i]);
                s_a[r * AROW + j2] = pcv;
            }
        }
        __syncthreads();
    }
}

// ============================================================================
// Launch
// ============================================================================
#define SCM_SMEM ((6680 + 16384) * 8)   // 184512 bytes

extern "C" void kernel_launch(void* const* d_in, const int* in_sizes, int n_in,
                              void* d_out, int out_size)
{
    const float* nz   = (const float*)d_in[0];
    const float* elog = (const float*)d_in[1];
    const float* emb  = (const float*)d_in[2];
    const float* paW  = (const float*)d_in[3];
    const float* pab  = (const float*)d_in[4];
    const float* mW1  = (const float*)d_in[5];
    const float* mb1  = (const float*)d_in[6];
    const float* mW2  = (const float*)d_in[7];
    const float* mb2  = (const float*)d_in[8];
    const float* mW3  = (const float*)d_in[9];
    const float* mb3  = (const float*)d_in[10];
    const float* neW  = (const float*)d_in[11];
    const float* neb  = (const float*)d_in[12];
    float* out = (float*)d_out;

    cudaFuncSetAttribute(scm_kernel, cudaFuncAttributeMaxDynamicSharedMemorySize, SCM_SMEM);

    pack_all_kernel<<<dim3(8, NV, 4), 256>>>(paW, mW1, mW2, mW3);
    noise_kernel<<<dim3(BATCH / 32, NV), 256>>>(nz, neW, neb);
    scm_kernel<<<NBLK, NT, SCM_SMEM>>>(elog, emb, pab, mb1, mb2, mb3, out);
}

// round 14
// speedup vs baseline: 1.1600x; 1.1600x over previous
#include <cuda_runtime.h>

// Problem constants
#define NV    32
#define DM    256
#define MM    128
#define DN    64
#define NL    3
#define BATCH 512
#define RPB   4                    // batch rows per block
#define NBLK  (BATCH / RPB)        // 128 blocks
#define NT    512                  // threads per block
#define AROW  130                  // activation buffer row stride (ull = float2)

// Scratch (device global: no allocations allowed)
__device__ float g_noise[BATCH * NV * DM];       // 16 MB: gelu(nz @ ne_W + ne_b)

typedef unsigned long long ull;

// ---- packed f32x2 helpers ----
__device__ __forceinline__ ull pack2(float w) {
    ull r; asm("mov.b64 %0, {%1, %1};" : "=l"(r) : "f"(w)); return r;
}
__device__ __forceinline__ ull pack2f(float a, float b) {
    ull r; asm("mov.b64 %0, {%1, %2};" : "=l"(r) : "f"(a), "f"(b)); return r;
}
__device__ __forceinline__ void ffma2(ull &acc, ull x, ull w) {
    asm("fma.rn.f32x2 %0, %1, %2, %3;" : "=l"(acc) : "l"(x), "l"(w), "l"(acc));
}
__device__ __forceinline__ ull fadd2(ull a, ull b) {
    ull r; asm("add.rn.f32x2 %0, %1, %2;" : "=l"(r) : "l"(a), "l"(b)); return r;
}
__device__ __forceinline__ float2 asf2(ull a) {
    float2 f; asm("mov.b64 {%0, %1}, %2;" : "=f"(f.x), "=f"(f.y) : "l"(a)); return f;
}
__device__ __forceinline__ float lanesum(ull a) {
    float2 f = asf2(a); return f.x + f.y;
}
__device__ __forceinline__ float gelu(float x) {
    return 0.5f * x * (1.0f + erff(x * 0.7071067811865476f));   // exact erf GELU
}

// ============================================================================
// Kernel: noise encoder precompute
// ============================================================================
__global__ void __launch_bounds__(256, 2) noise_kernel(
    const float* __restrict__ nz,
    const float* __restrict__ neW,
    const float* __restrict__ neb)
{
    const int i = blockIdx.y;
    const int chunk = blockIdx.x;
    const int d = threadIdx.x;

    __shared__ __align__(16) ull s_nzp[DN][16];
    for (int idx = d; idx < DN * 16; idx += 256) {
        int k = idx >> 4, rp = idx & 15;
        int b = chunk * 32 + rp * 2;
        s_nzp[k][rp] = pack2f(nz[(b * NV + i) * DN + k],
                              nz[((b + 1) * NV + i) * DN + k]);
    }
    __syncthreads();

    ull acc[16];
    #pragma unroll
    for (int rp = 0; rp < 16; rp++) acc[rp] = 0;

    const float* __restrict__ W = neW + i * DN * DM + d;
    #pragma unroll 2
    for (int k = 0; k < DN; k++) {
        ull w2 = pack2(__ldg(W + k * DM));
        const ulonglong2* row = reinterpret_cast<const ulonglong2*>(s_nzp[k]);
        #pragma unroll
        for (int j = 0; j < 8; j++) {
            ulonglong2 x = row[j];
            ffma2(acc[2 * j],     x.x, w2);
            ffma2(acc[2 * j + 1], x.y, w2);
        }
    }
    const float bias = neb[i * DM + d];
    #pragma unroll
    for (int rp = 0; rp < 16; rp++) {
        float2 f = asf2(acc[rp]);
        int b = chunk * 32 + rp * 2;
        g_noise[((long long)b * NV + i) * DM + d]       = gelu(f.x + bias);
        g_noise[((long long)(b + 1) * NV + i) * DM + d] = gelu(f.y + bias);
    }
}

// ============================================================================
// Split-K partial GEMM (R9 structure). Thread = (cg, ks): 4 cols x 4 rows.
// Weights read DIRECTLY from the row-major input W[k][N]: wE = even-k rows,
// wO = odd-k rows (the previously "packed" layout was the identity).
// Prefetch depth 2.
// ============================================================================
struct WPre { float4 e0, o0, e1, o1; };

template<int N, int K>
__device__ __forceinline__ WPre wpref(const float* __restrict__ Wp, int t)
{
    constexpr int CG = N / 4;
    constexpr int KS = NT / CG;
    constexpr int D2 = (K / KS) / 2;
    const int cg = t & (CG - 1);
    const int ks = t / CG;
    const int j0 = cg * 4;
    const float4* __restrict__ base =
        reinterpret_cast<const float4*>(Wp + (size_t)(ks * D2) * (2 * N) + j0);
    WPre p;
    p.e0 = __ldg(base);
    p.o0 = __ldg(base + N / 4);
    p.e1 = __ldg(base + N / 2);
    p.o1 = __ldg(base + 3 * (N / 4));
    return p;
}

template<int N, int K>
__device__ __forceinline__ void split_partial(
    const ull* __restrict__ sinu, float* __restrict__ red,
    const float* __restrict__ Wp, int t, WPre pre)
{
    constexpr int CG = N / 4;
    constexpr int KS = NT / CG;
    constexpr int D2 = (K / KS) / 2;
    const int cg = t & (CG - 1);
    const int ks = t / CG;
    const int j0 = cg * 4;

    ull acc[4][4];
    #pragma unroll
    for (int c = 0; c < 4; c++)
        #pragma unroll
        for (int r = 0; r < 4; r++) acc[c][r] = 0;

    const float4* __restrict__ wE =
        reinterpret_cast<const float4*>(Wp + (size_t)(ks * D2) * (2 * N) + j0);
    const float4* __restrict__ wO = wE + N / 4;
    const ull* __restrict__ x = sinu + ks * D2;

    #pragma unroll
    for (int d = 0; d < D2; d++) {
        float4 we = (d == 0) ? pre.e0 : (d == 1) ? pre.e1 : __ldg(wE + d * (N / 2));
        float4 wo = (d == 0) ? pre.o0 : (d == 1) ? pre.o1 : __ldg(wO + d * (N / 2));
        ull w0 = pack2f(we.x, wo.x);
        ull w1 = pack2f(we.y, wo.y);
        ull w2 = pack2f(we.z, wo.z);
        ull w3 = pack2f(we.w, wo.w);
        #pragma unroll
        for (int r = 0; r < 4; r++) {
            ull xv = x[r * AROW + d];
            ffma2(acc[0][r], xv, w0);
            ffma2(acc[1][r], xv, w1);
            ffma2(acc[2][r], xv, w2);
            ffma2(acc[3][r], xv, w3);
        }
    }
    #pragma unroll
    for (int r = 0; r < 4; r++) {
        float4 o = make_float4(lanesum(acc[0][r]), lanesum(acc[1][r]),
                               lanesum(acc[2][r]), lanesum(acc[3][r]));
        *reinterpret_cast<float4*>(red + (r * KS + ks) * N + j0) = o;
    }
}

// ---- reduce partials (tree) -> gelu -> activation buffer (float2 rows) ----
template<int N>
__device__ __forceinline__ void reduce_act(
    const float* __restrict__ red, ull* __restrict__ soutu,
    const float* __restrict__ bias, int t)
{
    constexpr int KS = 2048 / N;
    constexpr int J2 = N / 2;
    const int j2 = t & (J2 - 1);
    const int r  = (N == 256) ? (t >> 7) : (t >> 6);
    const ull* __restrict__ rp = reinterpret_cast<const ull*>(red);
    ull v[KS];
    #pragma unroll
    for (int k = 0; k < KS; k++)
        v[k] = rp[(r * KS + k) * J2 + j2];
    #pragma unroll
    for (int stride = KS / 2; stride > 0; stride >>= 1)
        #pragma unroll
        for (int k = 0; k < stride; k++)
            v[k] = fadd2(v[k], v[k + stride]);
    const float2 bb = __ldg(reinterpret_cast<const float2*>(bias) + j2);
    ull s = fadd2(v[0], pack2f(bb.x, bb.y));
    float2 f = asf2(s);
    soutu[r * AROW + j2] = pack2f(gelu(f.x), gelu(f.y));
}

// ---- pc partial for NEXT target variable (runs on idle upper threads) ----
__device__ __forceinline__ void pc_part(
    int half, int i, int tgt, int vmax,
    const float* __restrict__ s_val, const ull* __restrict__ s_adj2,
    const float* __restrict__ var_emb, ull* __restrict__ s_pc, int tu)
{
    const int id = half * 256 + tu;
    const int r  = id >> 7;
    const int j2 = id & 127;
    const float2 e = __ldg(reinterpret_cast<const float2*>(var_emb + tgt * DM) + j2);
    ull acc = pack2f(e.x, e.y);
    const float* vp = s_val + r * DM + j2 * 2;
    const ull* arow = s_adj2 + tgt * NV;
    #pragma unroll 4
    for (int v = 0; v < vmax; v++) {
        if (v == i) continue;                         // current var fused later
        ull x = *reinterpret_cast<const ull*>(vp + v * (4 * DM));
        ffma2(acc, x, arow[v]);
    }
    s_pc[r * AROW + j2] = acc;
}

// ============================================================================
// Main kernel
// ============================================================================
__global__ void __launch_bounds__(NT, 1) scm_kernel(
    const float* __restrict__ edge_logits,
    const float* __restrict__ var_emb,
    const float* __restrict__ paW,
    const float* __restrict__ pab,
    const float* __restrict__ mW1,
    const float* __restrict__ mb1,
    const float* __restrict__ mW2,
    const float* __restrict__ mb2,
    const float* __restrict__ mW3,
    const float* __restrict__ mb3,
    float* __restrict__ out)
{
    extern __shared__ __align__(16) ull smem[];
    float* s_red  = reinterpret_cast<float*>(smem);          // 4096 ull = 32KB
    ull*   s_a    = smem + 4096;                             // 520 ull
    ull*   s_b    = smem + 4616;                             // 520 ull
    ull*   s_pc   = smem + 5136;                             // 520 ull
    ull*   s_adj2 = smem + 5656;                             // 1024 ull
    float* s_val  = reinterpret_cast<float*>(smem + 6680);   // 32768 fl = 128KB

    const int t = threadIdx.x;
    const int row0 = blockIdx.x * RPB;

    // adjacency: sigmoid((logits * offdiag)/0.5); diagonal -> 0.5 (splat ull)
    for (int idx = t; idx < NV * NV; idx += NT) {
        int ii = idx / NV, v = idx % NV;
        float z = (v == ii) ? 0.0f : edge_logits[v * NV + ii] * 2.0f;
        s_adj2[idx] = pack2(1.0f / (1.0f + expf(-z)));
    }
    // step 0 input: s_a = emb[0]
    {
        const int j2 = t & 127;
        const int r  = t >> 7;
        const float2 e = __ldg(reinterpret_cast<const float2*>(var_emb) + j2);
        s_a[r * AROW + j2] = pack2f(e.x, e.y);
    }
    WPre pre_pa = wpref<DM, DM>(paW, t);
    __syncthreads();

    for (int s = 0; s < NL * NV; s++) {
        const int i = s & 31;
        const bool last = (s >= 2 * NV);
        const bool has_tgt = (s < NL * NV - 1);
        const int tgt = (i + 1) & 31;
        const int vmax = (s + 1 < NV) ? i : NV;

        // ---- pa: parent_input partials ; prefetch w1
        split_partial<DM, DM>(s_a, s_red, paW, t, pre_pa);
        WPre pre_w1 = wpref<MM, DM>(mW1 + i * (DM * MM), t);
        __syncthreads();

        reduce_act<DM>(s_red, s_b, pab, t);
        __syncthreads();

        // ---- w1: 256 -> 128 ; prefetch w2
        split_partial<MM, DM>(s_b, s_red, mW1 + i * (DM * MM), t, pre_w1);
        WPre pre_w2 = wpref<MM, MM>(mW2 + i * (MM * MM), t);
        __syncthreads();

        if (t < 256) reduce_act<MM>(s_red, s_a, mb1 + i * MM, t);
        else if (has_tgt) pc_part(0, i, tgt, vmax, s_val, s_adj2, var_emb, s_pc, t & 255);
        __syncthreads();

        // ---- w2: 128 -> 128 ; prefetch w3
        split_partial<MM, MM>(s_a, s_red, mW2 + i * (MM * MM), t, pre_w2);
        WPre pre_w3 = wpref<DM, MM>(mW3 + i * (MM * DM), t);
        __syncthreads();

        if (t < 256) reduce_act<MM>(s_red, s_b, mb2 + i * MM, t);
        else if (has_tgt) pc_part(1, i, tgt, vmax, s_val, s_adj2, var_emb, s_pc, t & 255);
        __syncthreads();

        // ---- w3: 128 -> 256 (partials) ; prefetch pa for next step
        split_partial<DM, MM>(s_b, s_red, mW3 + i * (MM * DM), t, pre_w3);
        pre_pa = wpref<DM, DM>(paW, t);
        __syncthreads();

        // ---- final: sum partials (tree) + bias + noise -> s_val, out (last),
        //      fuse pc: s_a = s_pc + adj[i->tgt] * val_new
        {
            const int j2 = t & 127;
            const int r  = t >> 7;
            const ull* rp = reinterpret_cast<const ull*>(s_red);
            ull v[8];
            #pragma unroll
            for (int k = 0; k < 8; k++)
                v[k] = rp[(r * 8 + k) * 128 + j2];
            #pragma unroll
            for (int stride = 4; stride > 0; stride >>= 1)
                #pragma unroll
                for (int k = 0; k < stride; k++)
                    v[k] = fadd2(v[k], v[k + stride]);
            const float2 b2 = __ldg(reinterpret_cast<const float2*>(mb3 + i * DM) + j2);
            long long gidx = ((long long)(row0 + r) * NV + i) * DM + j2 * 2;
            const float2 n2 = __ldg(reinterpret_cast<const float2*>(g_noise + gidx));
            float2 f = asf2(v[0]);
            float2 v2 = make_float2(f.x + b2.x + n2.x, f.y + b2.y + n2.y);
            *reinterpret_cast<float2*>(s_val + (i * 4 + r) * DM + j2 * 2) = v2;
            if (last) *reinterpret_cast<float2*>(out + gidx) = v2;
            if (has_tgt) {
                ull pcv = s_pc[r * AROW + j2];
                ffma2(pcv, pack2f(v2.x, v2.y), s_adj2[tgt * NV + i]);
                s_a[r * AROW + j2] = pcv;
            }
        }
        __syncthreads();
    }
}

// ============================================================================
// Launch
// ============================================================================
#define SCM_SMEM ((6680 + 16384) * 8)   // 184512 bytes

extern "C" void kernel_launch(void* const* d_in, const int* in_sizes, int n_in,
                              void* d_out, int out_size)
{
    const float* nz   = (const float*)d_in[0];
    const float* elog = (const float*)d_in[1];
    const float* emb  = (const float*)d_in[2];
    const float* paW  = (const float*)d_in[3];
    const float* pab  = (const float*)d_in[4];
    const float* mW1  = (const float*)d_in[5];
    const float* mb1  = (const float*)d_in[6];
    const float* mW2  = (const float*)d_in[7];
    const float* mb2  = (const float*)d_in[8];
    const float* mW3  = (const float*)d_in[9];
    const float* mb3  = (const float*)d_in[10];
    const float* neW  = (const float*)d_in[11];
    const float* neb  = (const float*)d_in[12];
    float* out = (float*)d_out;

    cudaFuncSetAttribute(scm_kernel, cudaFuncAttributeMaxDynamicSharedMemorySize, SCM_SMEM);

    noise_kernel<<<dim3(BATCH / 32, NV), 256>>>(nz, neW, neb);
    scm_kernel<<<NBLK, NT, SCM_SMEM>>>(elog, emb, paW, pab,
                                       mW1, mb1, mW2, mb2, mW3, mb3, out);
}

// round 15
// speedup vs baseline: 1.1693x; 1.0081x over previous
#include <cuda_runtime.h>

// Problem constants
#define NV    32
#define DM    256
#define MM    128
#define DN    64
#define NL    3
#define BATCH 512
#define RPB   4                    // batch rows per block
#define NBLK  (BATCH / RPB)        // 128 blocks
#define NT    512                  // threads per block
#define AROW  260                  // splat activation row stride (ull), even
#define PCROW 130                  // pc buffer row stride (ull, K-pair format)

// Scratch (device global: no allocations allowed)
__device__ float g_noise[BATCH * NV * DM];       // 16 MB: gelu(nz @ ne_W + ne_b)

typedef unsigned long long ull;

// ---- packed f32x2 helpers ----
__device__ __forceinline__ ull pack2(float w) {
    ull r; asm("mov.b64 %0, {%1, %1};" : "=l"(r) : "f"(w)); return r;
}
__device__ __forceinline__ ull pack2f(float a, float b) {
    ull r; asm("mov.b64 %0, {%1, %2};" : "=l"(r) : "f"(a), "f"(b)); return r;
}
__device__ __forceinline__ void ffma2(ull &acc, ull x, ull w) {
    asm("fma.rn.f32x2 %0, %1, %2, %3;" : "=l"(acc) : "l"(x), "l"(w), "l"(acc));
}
__device__ __forceinline__ ull fadd2(ull a, ull b) {
    ull r; asm("add.rn.f32x2 %0, %1, %2;" : "=l"(r) : "l"(a), "l"(b)); return r;
}
__device__ __forceinline__ float2 asf2(ull a) {
    float2 f; asm("mov.b64 {%0, %1}, %2;" : "=f"(f.x), "=f"(f.y) : "l"(a)); return f;
}
__device__ __forceinline__ float gelu(float x) {
    return 0.5f * x * (1.0f + erff(x * 0.7071067811865476f));   // exact erf GELU
}

// ============================================================================
// Kernel: noise encoder precompute
// ============================================================================
__global__ void __launch_bounds__(256, 2) noise_kernel(
    const float* __restrict__ nz,
    const float* __restrict__ neW,
    const float* __restrict__ neb)
{
    const int i = blockIdx.y;
    const int chunk = blockIdx.x;
    const int d = threadIdx.x;

    __shared__ __align__(16) ull s_nzp[DN][16];
    for (int idx = d; idx < DN * 16; idx += 256) {
        int k = idx >> 4, rp = idx & 15;
        int b = chunk * 32 + rp * 2;
        s_nzp[k][rp] = pack2f(nz[(b * NV + i) * DN + k],
                              nz[((b + 1) * NV + i) * DN + k]);
    }
    __syncthreads();

    ull acc[16];
    #pragma unroll
    for (int rp = 0; rp < 16; rp++) acc[rp] = 0;

    const float* __restrict__ W = neW + i * DN * DM + d;
    #pragma unroll 2
    for (int k = 0; k < DN; k++) {
        ull w2 = pack2(__ldg(W + k * DM));
        const ulonglong2* row = reinterpret_cast<const ulonglong2*>(s_nzp[k]);
        #pragma unroll
        for (int j = 0; j < 8; j++) {
            ulonglong2 x = row[j];
            ffma2(acc[2 * j],     x.x, w2);
            ffma2(acc[2 * j + 1], x.y, w2);
        }
    }
    const float bias = neb[i * DM + d];
    #pragma unroll
    for (int rp = 0; rp < 16; rp++) {
        float2 f = asf2(acc[rp]);
        int b = chunk * 32 + rp * 2;
        g_noise[((long long)b * NV + i) * DM + d]       = gelu(f.x + bias);
        g_noise[((long long)(b + 1) * NV + i) * DM + d] = gelu(f.y + bias);
    }
}

// ============================================================================
// Split-K partial GEMM, column-pair lanes. Thread = (cg, ks): 4 cols x 4 rows.
// Acts: splat ull per dim (broadcast LDS.64). Weights: one LDG.128 per k,
// consumed directly as two aligned f32x2 operands -> ZERO pack MOVs.
// Partials: (col-even,col-odd) lanes stored as STS.128; no lanesum.
// ============================================================================
struct WPre { ulonglong2 w0, w1; };   // first two k's weights

template<int N, int K>
__device__ __forceinline__ WPre wpref(const float* __restrict__ W, int t)
{
    constexpr int CG = N / 4;
    constexpr int KS = NT / CG;
    constexpr int KC = K / KS;
    const int cg = t & (CG - 1);
    const int ks = t / CG;
    const int j0 = cg * 4;
    const ulonglong2* __restrict__ base =
        reinterpret_cast<const ulonglong2*>(W + (size_t)(ks * KC) * N + j0);
    WPre p;
    p.w0 = __ldg(base);
    p.w1 = __ldg(base + N / 4);
    return p;
}

template<int N, int K>
__device__ __forceinline__ void split_partial(
    const ull* __restrict__ sinu, float* __restrict__ red,
    const float* __restrict__ W, int t, WPre pre)
{
    constexpr int CG = N / 4;
    constexpr int KS = NT / CG;
    constexpr int KC = K / KS;
    const int cg = t & (CG - 1);
    const int ks = t / CG;
    const int j0 = cg * 4;

    ull acc[2][4];                       // [colpair][row]
    #pragma unroll
    for (int c = 0; c < 2; c++)
        #pragma unroll
        for (int r = 0; r < 4; r++) acc[c][r] = 0;

    const ulonglong2* __restrict__ wq =
        reinterpret_cast<const ulonglong2*>(W + (size_t)(ks * KC) * N + j0);
    const ull* __restrict__ x = sinu + ks * KC;

    #pragma unroll
    for (int d = 0; d < KC; d++) {
        ulonglong2 wv = (d == 0) ? pre.w0 : (d == 1) ? pre.w1 : __ldg(wq + d * (N / 4));
        #pragma unroll
        for (int r = 0; r < 4; r++) {
            ull xv = x[r * AROW + d];    // broadcast LDS.64 splat
            ffma2(acc[0][r], xv, wv.x);
            ffma2(acc[1][r], xv, wv.y);
        }
    }
    #pragma unroll
    for (int r = 0; r < 4; r++)
        *reinterpret_cast<ulonglong2*>(red + (r * KS + ks) * N + j0) =
            make_ulonglong2(acc[0][r], acc[1][r]);
}

// ---- reduce partials (tree) -> gelu -> splat activation rows ----
// N=256: 512 threads (j2 = t&127, r = t>>7), KS=8
// N=128: 256 threads (j2 = t&63,  r = t>>6), KS=16
template<int N>
__device__ __forceinline__ void reduce_act(
    const float* __restrict__ red, ull* __restrict__ soutu,
    const float* __restrict__ bias, int t)
{
    constexpr int KS = 2048 / N;
    constexpr int J2 = N / 2;
    const int j2 = t & (J2 - 1);
    const int r  = (N == 256) ? (t >> 7) : (t >> 6);
    const ull* __restrict__ rp = reinterpret_cast<const ull*>(red);
    ull v[KS];
    #pragma unroll
    for (int k = 0; k < KS; k++)
        v[k] = rp[(r * KS + k) * (N / 2) + j2];
    #pragma unroll
    for (int stride = KS / 2; stride > 0; stride >>= 1)
        #pragma unroll
        for (int k = 0; k < stride; k++)
            v[k] = fadd2(v[k], v[k + stride]);
    const float2 bb = __ldg(reinterpret_cast<const float2*>(bias) + j2);
    ull s = fadd2(v[0], pack2f(bb.x, bb.y));
    float2 f = asf2(s);
    *reinterpret_cast<ulonglong2*>(soutu + r * AROW + 2 * j2) =
        make_ulonglong2(pack2(gelu(f.x)), pack2(gelu(f.y)));
}

// ---- pc partial for NEXT target (K-pair format, on idle upper threads) ----
__device__ __forceinline__ void pc_part(
    int half, int i, int tgt, int vmax,
    const float* __restrict__ s_val, const ull* __restrict__ s_adj2,
    const float* __restrict__ var_emb, ull* __restrict__ s_pc, int tu)
{
    const int id = half * 256 + tu;
    const int r  = id >> 7;
    const int j2 = id & 127;
    const float2 e = __ldg(reinterpret_cast<const float2*>(var_emb + tgt * DM) + j2);
    ull acc = pack2f(e.x, e.y);
    const float* vp = s_val + r * DM + j2 * 2;
    const ull* arow = s_adj2 + tgt * NV;
    #pragma unroll 4
    for (int v = 0; v < vmax; v++) {
        if (v == i) continue;                         // current var fused later
        ull x = *reinterpret_cast<const ull*>(vp + v * (4 * DM));
        ffma2(acc, x, arow[v]);
    }
    s_pc[r * PCROW + j2] = acc;
}

// ============================================================================
// Main kernel
// ============================================================================
__global__ void __launch_bounds__(NT, 1) scm_kernel(
    const float* __restrict__ edge_logits,
    const float* __restrict__ var_emb,
    const float* __restrict__ paW,
    const float* __restrict__ pab,
    const float* __restrict__ mW1,
    const float* __restrict__ mb1,
    const float* __restrict__ mW2,
    const float* __restrict__ mb2,
    const float* __restrict__ mW3,
    const float* __restrict__ mb3,
    float* __restrict__ out)
{
    extern __shared__ __align__(16) ull smem[];
    float* s_red  = reinterpret_cast<float*>(smem);          // 4096 ull = 32KB
    ull*   s_a    = smem + 4096;                             // 1040 ull (4 x AROW)
    ull*   s_b    = smem + 5136;                             // 1040 ull
    ull*   s_pc   = smem + 6176;                             // 520 ull
    ull*   s_adj2 = smem + 6696;                             // 1024 ull
    float* s_val  = reinterpret_cast<float*>(smem + 7720);   // 32768 fl = 128KB

    const int t = threadIdx.x;
    const int row0 = blockIdx.x * RPB;
    const int j2f = t & 127;
    const int rf  = t >> 7;

    // adjacency: sigmoid((logits * offdiag)/0.5); diagonal -> 0.5 (splat ull)
    for (int idx = t; idx < NV * NV; idx += NT) {
        int ii = idx / NV, v = idx % NV;
        float z = (v == ii) ? 0.0f : edge_logits[v * NV + ii] * 2.0f;
        s_adj2[idx] = pack2(1.0f / (1.0f + expf(-z)));
    }
    // step 0 input: s_a = splat(emb[0])
    {
        const float2 e = __ldg(reinterpret_cast<const float2*>(var_emb) + j2f);
        *reinterpret_cast<ulonglong2*>(s_a + rf * AROW + 2 * j2f) =
            make_ulonglong2(pack2(e.x), pack2(e.y));
    }
    WPre pre_pa = wpref<DM, DM>(paW, t);
    __syncthreads();

    for (int s = 0; s < NL * NV; s++) {
        const int i = s & 31;
        const bool last = (s >= 2 * NV);
        const bool has_tgt = (s < NL * NV - 1);
        const int tgt = (i + 1) & 31;
        const int vmax = (s + 1 < NV) ? i : NV;

        // ---- pa: parent_input partials ; prefetch w1
        split_partial<DM, DM>(s_a, s_red, paW, t, pre_pa);
        WPre pre_w1 = wpref<MM, DM>(mW1 + i * (DM * MM), t);
        __syncthreads();

        reduce_act<DM>(s_red, s_b, pab, t);
        __syncthreads();

        // ---- w1: 256 -> 128 ; prefetch w2
        split_partial<MM, DM>(s_b, s_red, mW1 + i * (DM * MM), t, pre_w1);
        WPre pre_w2 = wpref<MM, MM>(mW2 + i * (MM * MM), t);
        __syncthreads();

        if (t < 256) reduce_act<MM>(s_red, s_a, mb1 + i * MM, t);
        else if (has_tgt) pc_part(0, i, tgt, vmax, s_val, s_adj2, var_emb, s_pc, t & 255);
        __syncthreads();

        // ---- w2: 128 -> 128 ; prefetch w3
        split_partial<MM, MM>(s_a, s_red, mW2 + i * (MM * MM), t, pre_w2);
        WPre pre_w3 = wpref<DM, MM>(mW3 + i * (MM * DM), t);
        __syncthreads();

        if (t < 256) reduce_act<MM>(s_red, s_b, mb2 + i * MM, t);
        else if (has_tgt) pc_part(1, i, tgt, vmax, s_val, s_adj2, var_emb, s_pc, t & 255);
        __syncthreads();

        // ---- w3: 128 -> 256 (partials) ; prefetch pa for next step
        split_partial<DM, MM>(s_b, s_red, mW3 + i * (MM * DM), t, pre_w3);
        pre_pa = wpref<DM, DM>(paW, t);
        __syncthreads();

        // ---- final: sum partials (tree) + bias + noise -> s_val, out (last),
        //      fuse pc and write next step's splat input
        {
            const ull* rp = reinterpret_cast<const ull*>(s_red);
            ull v[8];
            #pragma unroll
            for (int k = 0; k < 8; k++)
                v[k] = rp[(rf * 8 + k) * 128 + j2f];
            #pragma unroll
            for (int stride = 4; stride > 0; stride >>= 1)
                #pragma unroll
                for (int k = 0; k < stride; k++)
                    v[k] = fadd2(v[k], v[k + stride]);
            const float2 b2 = __ldg(reinterpret_cast<const float2*>(mb3 + i * DM) + j2f);
            long long gidx = ((long long)(row0 + rf) * NV + i) * DM + j2f * 2;
            const float2 n2 = __ldg(reinterpret_cast<const float2*>(g_noise + gidx));
            float2 f = asf2(v[0]);
            float2 v2 = make_float2(f.x + b2.x + n2.x, f.y + b2.y + n2.y);
            *reinterpret_cast<float2*>(s_val + (i * 4 + rf) * DM + j2f * 2) = v2;
            if (last) *reinterpret_cast<float2*>(out + gidx) = v2;
            if (has_tgt) {
                ull pcv = s_pc[rf * PCROW + j2f];
                ffma2(pcv, pack2f(v2.x, v2.y), s_adj2[tgt * NV + i]);
                float2 pf = asf2(pcv);
                *reinterpret_cast<ulonglong2*>(s_a + rf * AROW + 2 * j2f) =
                    make_ulonglong2(pack2(pf.x), pack2(pf.y));
            }
        }
        __syncthreads();
    }
}

// ============================================================================
// Launch
// ============================================================================
#define SCM_SMEM ((7720 + 16384) * 8)   // 192832 bytes

extern "C" void kernel_launch(void* const* d_in, const int* in_sizes, int n_in,
                              void* d_out, int out_size)
{
    const float* nz   = (const float*)d_in[0];
    const float* elog = (const float*)d_in[1];
    const float* emb  = (const float*)d_in[2];
    const float* paW  = (const float*)d_in[3];
    const float* pab  = (const float*)d_in[4];
    const float* mW1  = (const float*)d_in[5];
    const float* mb1  = (const float*)d_in[6];
    const float* mW2  = (const float*)d_in[7];
    const float* mb2  = (const float*)d_in[8];
    const float* mW3  = (const float*)d_in[9];
    const float* mb3  = (const float*)d_in[10];
    const float* neW  = (const float*)d_in[11];
    const float* neb  = (const float*)d_in[12];
    float* out = (float*)d_out;

    cudaFuncSetAttribute(scm_kernel, cudaFuncAttributeMaxDynamicSharedMemorySize, SCM_SMEM);

    noise_kernel<<<dim3(BATCH / 32, NV), 256>>>(nz, neW, neb);
    scm_kernel<<<NBLK, NT, SCM_SMEM>>>(elog, emb, paW, pab,
                                       mW1, mb1, mW2, mb2, mW3, mb3, out);
}

// round 16
// speedup vs baseline: 1.1758x; 1.0055x over previous
#include <cuda_runtime.h>

// Problem constants
#define NV    32
#define DM    256
#define MM    128
#define DN    64
#define NL    3
#define BATCH 512
#define RPB   4                    // batch rows per block
#define NBLK  (BATCH / RPB)        // 128 blocks
#define NT    512                  // threads per block
#define AROW  260                  // splat activation row stride (ull), even
#define PCROW 130                  // pc buffer row stride (ull, K-pair format)

// Scratch (device global: no allocations allowed)
__device__ float g_noise[BATCH * NV * DM];       // 16 MB: gelu(nz @ ne_W + ne_b)

typedef unsigned long long ull;

// ---- packed f32x2 helpers ----
__device__ __forceinline__ ull pack2(float w) {
    ull r; asm("mov.b64 %0, {%1, %1};" : "=l"(r) : "f"(w)); return r;
}
__device__ __forceinline__ ull pack2f(float a, float b) {
    ull r; asm("mov.b64 %0, {%1, %2};" : "=l"(r) : "f"(a), "f"(b)); return r;
}
__device__ __forceinline__ void ffma2(ull &acc, ull x, ull w) {
    asm("fma.rn.f32x2 %0, %1, %2, %3;" : "=l"(acc) : "l"(x), "l"(w), "l"(acc));
}
__device__ __forceinline__ ull fadd2(ull a, ull b) {
    ull r; asm("add.rn.f32x2 %0, %1, %2;" : "=l"(r) : "l"(a), "l"(b)); return r;
}
__device__ __forceinline__ float2 asf2(ull a) {
    float2 f; asm("mov.b64 {%0, %1}, %2;" : "=f"(f.x), "=f"(f.y) : "l"(a)); return f;
}
__device__ __forceinline__ float gelu(float x) {
    return 0.5f * x * (1.0f + erff(x * 0.7071067811865476f));   // exact erf GELU
}

// ============================================================================
// Kernel: noise encoder precompute
// ============================================================================
__global__ void __launch_bounds__(256, 2) noise_kernel(
    const float* __restrict__ nz,
    const float* __restrict__ neW,
    const float* __restrict__ neb)
{
    const int i = blockIdx.y;
    const int chunk = blockIdx.x;
    const int d = threadIdx.x;

    __shared__ __align__(16) ull s_nzp[DN][16];
    for (int idx = d; idx < DN * 16; idx += 256) {
        int k = idx >> 4, rp = idx & 15;
        int b = chunk * 32 + rp * 2;
        s_nzp[k][rp] = pack2f(nz[(b * NV + i) * DN + k],
                              nz[((b + 1) * NV + i) * DN + k]);
    }
    __syncthreads();

    ull acc[16];
    #pragma unroll
    for (int rp = 0; rp < 16; rp++) acc[rp] = 0;

    const float* __restrict__ W = neW + i * DN * DM + d;
    #pragma unroll 2
    for (int k = 0; k < DN; k++) {
        ull w2 = pack2(__ldg(W + k * DM));
        const ulonglong2* row = reinterpret_cast<const ulonglong2*>(s_nzp[k]);
        #pragma unroll
        for (int j = 0; j < 8; j++) {
            ulonglong2 x = row[j];
            ffma2(acc[2 * j],     x.x, w2);
            ffma2(acc[2 * j + 1], x.y, w2);
        }
    }
    const float bias = neb[i * DM + d];
    #pragma unroll
    for (int rp = 0; rp < 16; rp++) {
        float2 f = asf2(acc[rp]);
        int b = chunk * 32 + rp * 2;
        g_noise[((long long)b * NV + i) * DM + d]       = gelu(f.x + bias);
        g_noise[((long long)(b + 1) * NV + i) * DM + d] = gelu(f.y + bias);
    }
}

// ============================================================================
// Split-K partial GEMM, column-pair lanes. Thread = (cg, ks): 4 cols x 4 rows.
// Acts: adjacent dim-splats read as ONE LDS.128 broadcast (2 dims per load).
// Weights: LDG.128 per k, consumed directly as two aligned f32x2 operands.
// Partials: (col-even,col-odd) lanes stored as STS.128.
// ============================================================================
struct WPre { ulonglong2 w0, w1; };   // k=0 and k=1 weights for this thread

template<int N, int K>
__device__ __forceinline__ WPre wpref(const float* __restrict__ W, int t)
{
    constexpr int CG = N / 4;
    constexpr int KS = NT / CG;
    constexpr int KC = K / KS;
    const int cg = t & (CG - 1);
    const int ks = t / CG;
    const int j0 = cg * 4;
    const ulonglong2* __restrict__ base =
        reinterpret_cast<const ulonglong2*>(W + (size_t)(ks * KC) * N + j0);
    WPre p;
    p.w0 = __ldg(base);
    p.w1 = __ldg(base + N / 4);
    return p;
}

template<int N, int K>
__device__ __forceinline__ void split_partial(
    const ull* __restrict__ sinu, float* __restrict__ red,
    const float* __restrict__ W, int t, WPre pre)
{
    constexpr int CG = N / 4;
    constexpr int KS = NT / CG;
    constexpr int KC = K / KS;
    const int cg = t & (CG - 1);
    const int ks = t / CG;
    const int j0 = cg * 4;

    ull acc[2][4];                       // [colpair][row]
    #pragma unroll
    for (int c = 0; c < 2; c++)
        #pragma unroll
        for (int r = 0; r < 4; r++) acc[c][r] = 0;

    const ulonglong2* __restrict__ wq =
        reinterpret_cast<const ulonglong2*>(W + (size_t)(ks * KC) * N + j0);
    const ull* __restrict__ x = sinu + ks * KC;

    #pragma unroll
    for (int d = 0; d < KC; d += 2) {
        ulonglong2 wv0 = (d == 0) ? pre.w0 : __ldg(wq + d * (N / 4));
        ulonglong2 wv1 = (d == 0) ? pre.w1 : __ldg(wq + (d + 1) * (N / 4));
        #pragma unroll
        for (int r = 0; r < 4; r++) {
            // one LDS.128 broadcast: splats of dims d and d+1 for row r
            ulonglong2 xv = *reinterpret_cast<const ulonglong2*>(x + r * AROW + d);
            ffma2(acc[0][r], xv.x, wv0.x);
            ffma2(acc[1][r], xv.x, wv0.y);
            ffma2(acc[0][r], xv.y, wv1.x);
            ffma2(acc[1][r], xv.y, wv1.y);
        }
    }
    #pragma unroll
    for (int r = 0; r < 4; r++)
        *reinterpret_cast<ulonglong2*>(red + (r * KS + ks) * N + j0) =
            make_ulonglong2(acc[0][r], acc[1][r]);
}

// ---- reduce partials (tree) -> gelu -> splat activation rows ----
template<int N>
__device__ __forceinline__ void reduce_act(
    const float* __restrict__ red, ull* __restrict__ soutu,
    const float* __restrict__ bias, int t)
{
    constexpr int KS = 2048 / N;
    constexpr int J2 = N / 2;
    const int j2 = t & (J2 - 1);
    const int r  = (N == 256) ? (t >> 7) : (t >> 6);
    const ull* __restrict__ rp = reinterpret_cast<const ull*>(red);
    ull v[KS];
    #pragma unroll
    for (int k = 0; k < KS; k++)
        v[k] = rp[(r * KS + k) * (N / 2) + j2];
    #pragma unroll
    for (int stride = KS / 2; stride > 0; stride >>= 1)
        #pragma unroll
        for (int k = 0; k < stride; k++)
            v[k] = fadd2(v[k], v[k + stride]);
    const float2 bb = __ldg(reinterpret_cast<const float2*>(bias) + j2);
    ull s = fadd2(v[0], pack2f(bb.x, bb.y));
    float2 f = asf2(s);
    *reinterpret_cast<ulonglong2*>(soutu + r * AROW + 2 * j2) =
        make_ulonglong2(pack2(gelu(f.x)), pack2(gelu(f.y)));
}

// ---- pc partial for NEXT target (K-pair format, on idle upper threads) ----
__device__ __forceinline__ void pc_part(
    int half, int i, int tgt, int vmax,
    const float* __restrict__ s_val, const ull* __restrict__ s_adj2,
    const float* __restrict__ var_emb, ull* __restrict__ s_pc, int tu)
{
    const int id = half * 256 + tu;
    const int r  = id >> 7;
    const int j2 = id & 127;
    const float2 e = __ldg(reinterpret_cast<const float2*>(var_emb + tgt * DM) + j2);
    ull acc = pack2f(e.x, e.y);
    const float* vp = s_val + r * DM + j2 * 2;
    const ull* arow = s_adj2 + tgt * NV;
    #pragma unroll 4
    for (int v = 0; v < vmax; v++) {
        if (v == i) continue;                         // current var fused later
        ull x = *reinterpret_cast<const ull*>(vp + v * (4 * DM));
        ffma2(acc, x, arow[v]);
    }
    s_pc[r * PCROW + j2] = acc;
}

// ============================================================================
// Main kernel
// ============================================================================
__global__ void __launch_bounds__(NT, 1) scm_kernel(
    const float* __restrict__ edge_logits,
    const float* __restrict__ var_emb,
    const float* __restrict__ paW,
    const float* __restrict__ pab,
    const float* __restrict__ mW1,
    const float* __restrict__ mb1,
    const float* __restrict__ mW2,
    const float* __restrict__ mb2,
    const float* __restrict__ mW3,
    const float* __restrict__ mb3,
    float* __restrict__ out)
{
    extern __shared__ __align__(16) ull smem[];
    float* s_red  = reinterpret_cast<float*>(smem);          // 4096 ull = 32KB
    ull*   s_a    = smem + 4096;                             // 1040 ull (4 x AROW)
    ull*   s_b    = smem + 5136;                             // 1040 ull
    ull*   s_pc   = smem + 6176;                             // 520 ull
    ull*   s_adj2 = smem + 6696;                             // 1024 ull
    float* s_val  = reinterpret_cast<float*>(smem + 7720);   // 32768 fl = 128KB

    const int t = threadIdx.x;
    const int row0 = blockIdx.x * RPB;
    const int j2f = t & 127;
    const int rf  = t >> 7;

    // adjacency: sigmoid((logits * offdiag)/0.5); diagonal -> 0.5 (splat ull)
    for (int idx = t; idx < NV * NV; idx += NT) {
        int ii = idx / NV, v = idx % NV;
        float z = (v == ii) ? 0.0f : edge_logits[v * NV + ii] * 2.0f;
        s_adj2[idx] = pack2(1.0f / (1.0f + expf(-z)));
    }
    // step 0 input: s_a = splat(emb[0])
    {
        const float2 e = __ldg(reinterpret_cast<const float2*>(var_emb) + j2f);
        *reinterpret_cast<ulonglong2*>(s_a + rf * AROW + 2 * j2f) =
            make_ulonglong2(pack2(e.x), pack2(e.y));
    }
    WPre pre_pa = wpref<DM, DM>(paW, t);
    __syncthreads();

    for (int s = 0; s < NL * NV; s++) {
        const int i = s & 31;
        const bool last = (s >= 2 * NV);
        const bool has_tgt = (s < NL * NV - 1);
        const int tgt = (i + 1) & 31;
        const int vmax = (s + 1 < NV) ? i : NV;

        // ---- pa: parent_input partials ; prefetch w1
        split_partial<DM, DM>(s_a, s_red, paW, t, pre_pa);
        WPre pre_w1 = wpref<MM, DM>(mW1 + i * (DM * MM), t);
        __syncthreads();

        reduce_act<DM>(s_red, s_b, pab, t);
        __syncthreads();

        // ---- w1: 256 -> 128 ; prefetch w2
        split_partial<MM, DM>(s_b, s_red, mW1 + i * (DM * MM), t, pre_w1);
        WPre pre_w2 = wpref<MM, MM>(mW2 + i * (MM * MM), t);
        __syncthreads();

        if (t < 256) reduce_act<MM>(s_red, s_a, mb1 + i * MM, t);
        else if (has_tgt) pc_part(0, i, tgt, vmax, s_val, s_adj2, var_emb, s_pc, t & 255);
        __syncthreads();

        // ---- w2: 128 -> 128 ; prefetch w3
        split_partial<MM, MM>(s_a, s_red, mW2 + i * (MM * MM), t, pre_w2);
        WPre pre_w3 = wpref<DM, MM>(mW3 + i * (MM * DM), t);
        __syncthreads();

        if (t < 256) reduce_act<MM>(s_red, s_b, mb2 + i * MM, t);
        else if (has_tgt) pc_part(1, i, tgt, vmax, s_val, s_adj2, var_emb, s_pc, t & 255);
        __syncthreads();

        // ---- w3: 128 -> 256 (partials) ; prefetch pa for next step
        split_partial<DM, MM>(s_b, s_red, mW3 + i * (MM * DM), t, pre_w3);
        pre_pa = wpref<DM, DM>(paW, t);
        __syncthreads();

        // ---- final: sum partials (tree) + bias + noise -> s_val, out (last),
        //      fuse pc and write next step's splat input
        {
            const ull* rp = reinterpret_cast<const ull*>(s_red);
            ull v[8];
            #pragma unroll
            for (int k = 0; k < 8; k++)
                v[k] = rp[(rf * 8 + k) * 128 + j2f];
            #pragma unroll
            for (int stride = 4; stride > 0; stride >>= 1)
                #pragma unroll
                for (int k = 0; k < stride; k++)
                    v[k] = fadd2(v[k], v[k + stride]);
            const float2 b2 = __ldg(reinterpret_cast<const float2*>(mb3 + i * DM) + j2f);
            long long gidx = ((long long)(row0 + rf) * NV + i) * DM + j2f * 2;
            const float2 n2 = __ldg(reinterpret_cast<const float2*>(g_noise + gidx));
            float2 f = asf2(v[0]);
            float2 v2 = make_float2(f.x + b2.x + n2.x, f.y + b2.y + n2.y);
            *reinterpret_cast<float2*>(s_val + (i * 4 + rf) * DM + j2f * 2) = v2;
            if (last) *reinterpret_cast<float2*>(out + gidx) = v2;
            if (has_tgt) {
                ull pcv = s_pc[rf * PCROW + j2f];
                ffma2(pcv, pack2f(v2.x, v2.y), s_adj2[tgt * NV + i]);
                float2 pf = asf2(pcv);
                *reinterpret_cast<ulonglong2*>(s_a + rf * AROW + 2 * j2f) =
                    make_ulonglong2(pack2(pf.x), pack2(pf.y));
            }
        }
        __syncthreads();
    }
}

// ============================================================================
// Launch
// ============================================================================
#define SCM_SMEM ((7720 + 16384) * 8)   // 192832 bytes

extern "C" void kernel_launch(void* const* d_in, const int* in_sizes, int n_in,
                              void* d_out, int out_size)
{
    const float* nz   = (const float*)d_in[0];
    const float* elog = (const float*)d_in[1];
    const float* emb  = (const float*)d_in[2];
    const float* paW  = (const float*)d_in[3];
    const float* pab  = (const float*)d_in[4];
    const float* mW1  = (const float*)d_in[5];
    const float* mb1  = (const float*)d_in[6];
    const float* mW2  = (const float*)d_in[7];
    const float* mb2  = (const float*)d_in[8];
    const float* mW3  = (const float*)d_in[9];
    const float* mb3  = (const float*)d_in[10];
    const float* neW  = (const float*)d_in[11];
    const float* neb  = (const float*)d_in[12];
    float* out = (float*)d_out;

    cudaFuncSetAttribute(scm_kernel, cudaFuncAttributeMaxDynamicSharedMemorySize, SCM_SMEM);

    noise_kernel<<<dim3(BATCH / 32, NV), 256>>>(nz, neW, neb);
    scm_kernel<<<NBLK, NT, SCM_SMEM>>>(elog, emb, paW, pab,
                                       mW1, mb1, mW2, mb2, mW3, mb3, out);
}